// round 6
// baseline (speedup 1.0000x reference)
#include <cuda_runtime.h>
#include <cstdint>

#define N_PULSES 64
#define N_STATES 21

__global__ __launch_bounds__(256)
void epg_kernel(const float* __restrict__ flip,
                const float* __restrict__ phases,
                const float* __restrict__ T1,
                const float* __restrict__ T2,
                const float* __restrict__ B0,
                const float* __restrict__ B1,
                const void*  __restrict__ trp,
                float* __restrict__ out,
                int B)
{
    // Per-pulse constants: (cb, sb, c2b, s2b) in one float4 (LDS.128), half-angle separate
    __shared__ float4 s_c[N_PULSES];
    __shared__ float  s_ha[N_PULSES];

    int tid = threadIdx.x;
    if (tid < N_PULSES) {
        float bph = phases[tid];
        float sb, cb;
        sincosf(bph, &sb, &cb);
        s_c[tid]  = make_float4(cb, sb, cb * cb - sb * sb, 2.0f * cb * sb);
        s_ha[tid] = 0.5f * flip[tid];
    }
    __syncthreads();

    int gwarp = (int)((blockIdx.x * blockDim.x + tid) >> 5);
    int lane  = tid & 31;
    if (gwarp >= B) return;
    int b = gwarp;

    // TR: defensive decode (int32 / float32 both yield 500)
    float TRf;
    {
        int iv = *(const int*)trp;
        if (iv > 0 && iv < 1000000) TRf = (float)iv;
        else                        TRf = *(const float*)trp;
    }

    float t1v = T1[b], t2v = T2[b], b0v = B0[b], b1v = B1[b];
    float E1 = expf(-TRf / t1v);
    float E2 = expf(-TRf / t2v);
    float one_mE1 = 1.0f - E1;

    float phi = 2.0f * 3.14159265358979f * b0v * TRf * 0.001f;
    float sphi, cphi;
    sincosf(phi, &sphi, &cphi);

    // Fused relaxation + off-resonance: Fp *= E2*e^{+i phi}, Fm *= E2*e^{-i phi}
    float cE = E2 * cphi;
    float sE = E2 * sphi;

    // State (per lane = per EPG order). Lanes >= N_STATES carry junk but stay in lockstep.
    float FpR = 0.f, FpI = 0.f, FmR = 0.f, FmI = 0.f;
    float Z = (lane == 0) ? 1.0f : 0.0f;

    size_t planeStride = (size_t)B * N_STATES;     // elements
    size_t pulseStride = 5 * planeStride;
    float* outp = out + (size_t)b * N_STATES + lane;
    bool doStore = (lane < N_STATES);
    bool isLane0 = (lane == 0);
    bool isLast  = (lane == N_STATES - 1);

    #pragma unroll 4
    for (int p = 0; p < N_PULSES; p++) {
        // Fused E2 relaxation + B0 rotation (one complex multiply each)
        float r;
        r   = FpR * cE - FpI * sE;
        FpI = FpR * sE + FpI * cE;
        FpR = r;
        r   = FmR * cE + FmI * sE;
        FmI = FmI * cE - FmR * sE;
        FmR = r;

        // Z relaxation + recovery (lane 0 only)
        Z *= E1;
        if (isLane0) Z += one_mE1;

        // RF pulse mixing — hardware sincos
        float sa, ca;
        __sincosf(s_ha[p] * b1v, &sa, &ca);
        float4 c = s_c[p];
        float cb = c.x, sb = c.y, c2b = c.z, s2b = c.w;
        float ca2 = ca * ca, sa2 = sa * sa, casa = ca * sa;
        float cZ   = casa * Z;
        float cZsb = cZ * sb;
        float cZcb = cZ * cb;

        float FpnR = ca2 * FpR + sa2 * ( FmR * c2b + FmI * s2b) - cZsb;
        float FpnI = ca2 * FpI + sa2 * ( FmR * s2b - FmI * c2b) + cZcb;
        float FmnR = ca2 * FmR + sa2 * ( FpR * c2b - FpI * s2b) - cZsb;
        float FmnI = ca2 * FmI + sa2 * (-FpR * s2b - FpI * c2b) - cZcb;
        float Dim  = (FpI * cb - FpR * sb) - (FmR * sb + FmI * cb);
        float Zn   = casa * Dim + (ca2 - sa2) * Z;

        // Gradient shift: Fp states move up one order, Fm down one order
        float FpsR = __shfl_up_sync(0xffffffffu, FpnR, 1);
        float FpsI = __shfl_up_sync(0xffffffffu, FpnI, 1);
        float FmsR = __shfl_down_sync(0xffffffffu, FmnR, 1);
        float FmsI = __shfl_down_sync(0xffffffffu, FmnI, 1);
        if (isLane0) { FpsR = 0.f; FpsI = 0.f; }
        if (isLast)  { FmsR = 0.f; FmsI = 0.f; }
        FpR = FpsR; FpI = FpsI; FmR = FmsR; FmI = FmsI; Z = Zn;

        // Store outs[p, 0..4, b, lane] — immediate-offset stores off one pointer
        if (doStore) {
            outp[0]               = FpR;
            outp[planeStride]     = FpI;
            outp[2 * planeStride] = FmR;
            outp[3 * planeStride] = FmI;
            outp[4 * planeStride] = Zn;
        }
        outp += pulseStride;
    }
}

extern "C" void kernel_launch(void* const* d_in, const int* in_sizes, int n_in,
                              void* d_out, int out_size)
{
    const float* flip   = (const float*)d_in[0];
    const float* phases = (const float*)d_in[1];
    const float* T1     = (const float*)d_in[2];
    const float* T2     = (const float*)d_in[3];
    const float* B0     = (const float*)d_in[4];
    const float* B1     = (const float*)d_in[5];
    const void*  trp    = d_in[6];
    float* out = (float*)d_out;

    int B = in_sizes[2];               // batch from T1
    int threads = 256;
    int warpsPerBlock = threads / 32;
    int blocks = (B + warpsPerBlock - 1) / warpsPerBlock;

    epg_kernel<<<blocks, threads>>>(flip, phases, T1, T2, B0, B1, trp, out, B);
}

// round 7
// speedup vs baseline: 1.2591x; 1.2591x over previous
#include <cuda_runtime.h>
#include <cstdint>

#define N_PULSES 64
#define N_STATES 21

__global__ __launch_bounds__(256)
void epg_kernel(const float* __restrict__ flip,
                const float* __restrict__ phases,
                const float* __restrict__ T1,
                const float* __restrict__ T2,
                const float* __restrict__ B0,
                const float* __restrict__ B1,
                const void*  __restrict__ trp,
                float* __restrict__ out,
                int B)
{
    // Per-pulse trig, computed once per block (5 scalar arrays — R2 structure)
    __shared__ float s_cb[N_PULSES], s_sb[N_PULSES], s_c2b[N_PULSES], s_s2b[N_PULSES], s_ha[N_PULSES];

    int tid = threadIdx.x;
    if (tid < N_PULSES) {
        float bph = phases[tid];
        float sb, cb;
        sincosf(bph, &sb, &cb);
        s_cb[tid]  = cb;
        s_sb[tid]  = sb;
        s_c2b[tid] = cb * cb - sb * sb;
        s_s2b[tid] = 2.0f * cb * sb;
        s_ha[tid]  = 0.5f * flip[tid];
    }
    __syncthreads();

    int gwarp = (int)((blockIdx.x * blockDim.x + tid) >> 5);
    int lane  = tid & 31;
    if (gwarp >= B) return;
    int b = gwarp;

    // TR: defensive decode (int32 / float32 both yield 500)
    float TRf;
    {
        int iv = *(const int*)trp;
        if (iv > 0 && iv < 1000000) TRf = (float)iv;
        else                        TRf = *(const float*)trp;
    }

    float t1v = T1[b], t2v = T2[b], b0v = B0[b], b1v = B1[b];
    float E1 = expf(-TRf / t1v);
    float E2 = expf(-TRf / t2v);
    float recov = (lane == 0) ? (1.0f - E1) : 0.0f;   // unpredicated FFMA operand

    float phi = 2.0f * 3.14159265358979f * b0v * TRf * 0.001f;
    float sphi, cphi;
    sincosf(phi, &sphi, &cphi);

    // Fused relaxation + off-resonance: Fp *= E2*e^{+i phi}, Fm *= E2*e^{-i phi}
    float cE = E2 * cphi;
    float sE = E2 * sphi;

    // State (per lane = per EPG order). Lanes >= N_STATES carry junk but stay in lockstep.
    float FpR = 0.f, FpI = 0.f, FmR = 0.f, FmI = 0.f;
    float Z = (lane == 0) ? 1.0f : 0.0f;

    size_t planeStride = (size_t)B * N_STATES;
    float* outp = out + (size_t)b * N_STATES + lane;

    #pragma unroll 4
    for (int p = 0; p < N_PULSES; p++) {
        // Fused E2 relaxation + B0 rotation (one complex multiply each)
        float r;
        r   = FpR * cE - FpI * sE;
        FpI = FpR * sE + FpI * cE;
        FpR = r;
        r   = FmR * cE + FmI * sE;
        FmI = FmI * cE - FmR * sE;
        FmR = r;

        // Z relaxation + recovery in one FFMA (recov is 0 except lane 0)
        Z = Z * E1 + recov;

        // RF pulse mixing — hardware sincos
        float sa, ca;
        __sincosf(s_ha[p] * b1v, &sa, &ca);
        float cb  = s_cb[p],  sb  = s_sb[p];
        float c2b = s_c2b[p], s2b = s_s2b[p];
        float ca2 = ca * ca, sa2 = sa * sa, casa = ca * sa;
        float cZ   = casa * Z;
        float cZsb = cZ * sb;
        float cZcb = cZ * cb;

        float FpnR = ca2 * FpR + sa2 * ( FmR * c2b + FmI * s2b) - cZsb;
        float FpnI = ca2 * FpI + sa2 * ( FmR * s2b - FmI * c2b) + cZcb;
        float FmnR = ca2 * FmR + sa2 * ( FpR * c2b - FpI * s2b) - cZsb;
        float FmnI = ca2 * FmI + sa2 * (-FpR * s2b - FpI * c2b) - cZcb;
        float Dim  = (FpI * cb - FpR * sb) - (FmR * sb + FmI * cb);
        float Zn   = casa * Dim + (ca2 - sa2) * Z;

        // Gradient shift: Fp states move up one order, Fm down one order
        float FpsR = __shfl_up_sync(0xffffffffu, FpnR, 1);
        float FpsI = __shfl_up_sync(0xffffffffu, FpnI, 1);
        float FmsR = __shfl_down_sync(0xffffffffu, FmnR, 1);
        float FmsI = __shfl_down_sync(0xffffffffu, FmnI, 1);
        if (lane == 0)            { FpsR = 0.f; FpsI = 0.f; }
        if (lane == N_STATES - 1) { FmsR = 0.f; FmsI = 0.f; }
        FpR = FpsR; FpI = FpsI; FmR = FmsR; FmI = FmsI; Z = Zn;

        // Store outs[p, 0..4, b, lane] — per-iteration independent addresses (R2 structure)
        if (lane < N_STATES) {
            float* o = outp + (size_t)(p * 5) * planeStride;
            o[0]               = FpR;
            o[planeStride]     = FpI;
            o[2 * planeStride] = FmR;
            o[3 * planeStride] = FmI;
            o[4 * planeStride] = Zn;
        }
    }
}

extern "C" void kernel_launch(void* const* d_in, const int* in_sizes, int n_in,
                              void* d_out, int out_size)
{
    const float* flip   = (const float*)d_in[0];
    const float* phases = (const float*)d_in[1];
    const float* T1     = (const float*)d_in[2];
    const float* T2     = (const float*)d_in[3];
    const float* B0     = (const float*)d_in[4];
    const float* B1     = (const float*)d_in[5];
    const void*  trp    = d_in[6];
    float* out = (float*)d_out;

    int B = in_sizes[2];               // batch from T1
    int threads = 256;
    int warpsPerBlock = threads / 32;
    int blocks = (B + warpsPerBlock - 1) / warpsPerBlock;

    epg_kernel<<<blocks, threads>>>(flip, phases, T1, T2, B0, B1, trp, out, B);
}